// round 3
// baseline (speedup 1.0000x reference)
#include <cuda_runtime.h>
#include <cuda_fp16.h>
#include <mma.h>

using namespace nvcuda;

#define NN   3000
#define TT   64
#define DDYN 5
#define RR   128

// ---------------- scratch (device globals; no allocations) ----------------
__device__ float  g_svec[6 * NN];                       // pop1,pop2,demo1,demo2,eco1,eco2
__device__ float  g_xs[(size_t)NN * TT * DDYN];         // total_weights * dynamic
__device__ __half g_hseq[(size_t)NN * TT * RR];         // LSTM hidden sequence (fp16)

// ---------------- math helpers ----------------
__device__ __forceinline__ float sigm(float x) {
    return __fdividef(1.f, 1.f + __expf(-x));
}
__device__ __forceinline__ float tanh_acc(float x) {
    return fmaf(2.f, sigm(2.f * x), -1.f);
}
__device__ __forceinline__ float leaky(float x) { return x >= 0.f ? x : 0.01f * x; }

// ---------------- kernel 1: rank-1 pair-score vectors ----------------
template <int D>
__device__ __forceinline__ void pair_s(const float* __restrict__ x,
                                       const float* __restrict__ W,
                                       const float* __restrict__ a,
                                       float& s1, float& s2) {
    float xv[D];
#pragma unroll
    for (int k = 0; k < D; k++) xv[k] = x[k];
    float t1 = 0.f, t2 = 0.f;
    for (int j = 0; j < D; j++) {
        float h = 0.f;
#pragma unroll
        for (int k = 0; k < D; k++) h = fmaf(xv[k], W[k * D + j], h);
        t1 = fmaf(h, a[j], t1);
        t2 = fmaf(h, a[D + j], t2);
    }
    s1 = t1; s2 = t2;
}

__global__ void svec_kernel(const float* __restrict__ pop, const float* __restrict__ demo,
                            const float* __restrict__ eco,
                            const float* __restrict__ W_pop, const float* __restrict__ a_pop,
                            const float* __restrict__ W_demo, const float* __restrict__ a_demo,
                            const float* __restrict__ W_eco, const float* __restrict__ a_eco) {
    int i = blockIdx.x * blockDim.x + threadIdx.x;
    if (i >= NN) return;
    float s1, s2;
    pair_s<16>(pop + i * 16, W_pop, a_pop, s1, s2);
    g_svec[0 * NN + i] = s1; g_svec[1 * NN + i] = s2;
    pair_s<32>(demo + i * 32, W_demo, a_demo, s1, s2);
    g_svec[2 * NN + i] = s1; g_svec[3 * NN + i] = s2;
    pair_s<16>(eco + i * 16, W_eco, a_eco, s1, s2);
    g_svec[4 * NN + i] = s1; g_svec[5 * NN + i] = s2;
}

// ---------------- kernel 2: fused score + softmax -> dist ----------------
__global__ __launch_bounds__(256) void dist_kernel(const float* __restrict__ geo,
                                                   const float* __restrict__ W_geo,
                                                   const float* __restrict__ a_geo,
                                                   float* __restrict__ dist) {
    const int i = blockIdx.x;
    const int tid = threadIdx.x;
    const float v0 = fmaf(W_geo[0], a_geo[0], W_geo[1] * a_geo[1]);
    const float v1 = fmaf(W_geo[2], a_geo[0], W_geo[3] * a_geo[1]);
    const float sp1 = g_svec[0 * NN + i];
    const float sd1 = g_svec[2 * NN + i];
    const float se1 = g_svec[4 * NN + i];
    const float2* grow = reinterpret_cast<const float2*>(geo) + (size_t)i * NN;

    float ev[12];
    float sum = 0.f;
#pragma unroll
    for (int k2 = 0; k2 < 12; k2++) {
        int j = tid + (k2 << 8);
        float e = 0.f;
        if (j < NN) {
            float2 g = __ldg(grow + j);
            float sg = fmaf(g.x, v0, g.y * v1);
            float a = sigm(sp1 + g_svec[1 * NN + j])
                    + sigm(sd1 + g_svec[3 * NN + j])
                    + sigm(se1 + g_svec[5 * NN + j])
                    + sigm(sg);
            e = __expf(a);
        }
        ev[k2] = e;
        sum += e;
    }
#pragma unroll
    for (int o = 16; o > 0; o >>= 1) sum += __shfl_xor_sync(0xffffffffu, sum, o);
    __shared__ float red[8];
    __shared__ float stot;
    if ((tid & 31) == 0) red[tid >> 5] = sum;
    __syncthreads();
    if (tid == 0) {
        float t2 = 0.f;
#pragma unroll
        for (int w = 0; w < 8; w++) t2 += red[w];
        stot = __fdividef(1.f, t2);
    }
    __syncthreads();
    const float inv = stot;
    float* drow = dist + (size_t)i * NN;
#pragma unroll
    for (int k2 = 0; k2 < 12; k2++) {
        int j = tid + (k2 << 8);
        if (j < NN) drow[j] = ev[k2] * inv;
    }
}

// ---------------- kernel 3: total_weights MLPs + scaled LSTM input ----------------
__global__ __launch_bounds__(256) void tw_kernel(const float* __restrict__ dyn,
        const float* __restrict__ cw_w1, const float* __restrict__ cw_b1,
        const float* __restrict__ cw_w2, const float* __restrict__ cw_b2,
        const float* __restrict__ hw_w1, const float* __restrict__ hw_b1,
        const float* __restrict__ hw_w2, const float* __restrict__ hw_b2,
        float* __restrict__ tw) {
    __shared__ float s_c1[128], s_cb1[128], s_c2[128];
    __shared__ float s_h1[4 * 128], s_hb1[128], s_h2[128 * 4];
    __shared__ float s_cb2, s_hb2[4];
    const int tid = threadIdx.x;
    for (int idx = tid; idx < 128; idx += 256) {
        s_c1[idx] = cw_w1[idx]; s_cb1[idx] = cw_b1[idx];
        s_c2[idx] = cw_w2[idx]; s_hb1[idx] = hw_b1[idx];
    }
    for (int idx = tid; idx < 512; idx += 256) { s_h1[idx] = hw_w1[idx]; s_h2[idx] = hw_w2[idx]; }
    if (tid == 0) s_cb2 = cw_b2[0];
    if (tid < 4) s_hb2[tid] = hw_b2[tid];
    __syncthreads();

    const int idx = blockIdx.x * 256 + tid;
    if (idx >= NN * TT) return;
    const float* d = dyn + (size_t)idx * DDYN;
    const float x0 = d[0], x1 = d[1], x2 = d[2], x3 = d[3], x4 = d[4];
    float ca = 0.f, o0 = 0.f, o1 = 0.f, o2 = 0.f, o3 = 0.f;
#pragma unroll 4
    for (int r = 0; r < 128; r++) {
        float hc = fmaf(x0, s_c1[r], s_cb1[r]);
        hc = leaky(hc);
        ca = fmaf(hc, s_c2[r], ca);
        float hh = s_hb1[r];
        hh = fmaf(x1, s_h1[r], hh);
        hh = fmaf(x2, s_h1[128 + r], hh);
        hh = fmaf(x3, s_h1[256 + r], hh);
        hh = fmaf(x4, s_h1[384 + r], hh);
        hh = leaky(hh);
        o0 = fmaf(hh, s_h2[r * 4 + 0], o0);
        o1 = fmaf(hh, s_h2[r * 4 + 1], o1);
        o2 = fmaf(hh, s_h2[r * 4 + 2], o2);
        o3 = fmaf(hh, s_h2[r * 4 + 3], o3);
    }
    const float w0 = sigm(ca + s_cb2);
    const float w1 = sigm(o0 + s_hb2[0]);
    const float w2 = sigm(o1 + s_hb2[1]);
    const float w3 = sigm(o2 + s_hb2[2]);
    const float w4 = sigm(o3 + s_hb2[3]);
    float* twp = tw + (size_t)idx * DDYN;
    twp[0] = w0; twp[1] = w1; twp[2] = w2; twp[3] = w3; twp[4] = w4;
    float* xp = g_xs + (size_t)idx * DDYN;
    xp[0] = w0 * x0; xp[1] = w1 * x1; xp[2] = w2 * x2; xp[3] = w3 * x3; xp[4] = w4 * x4;
}

// ---------------- kernel 4: persistent fp16-mma LSTM ----------------
#define LS_B_OFF    0                              // half [128][520]
#define LS_AST_OFF  (LS_B_OFF + 128 * 520 * 2)     // half [32][136]
#define LS_WIH_OFF  (LS_AST_OFF + 32 * 136 * 2)    // float [5][512]
#define LS_BIAS_OFF (LS_WIH_OFF + 5 * 512 * 4)     // float [512]
#define LS_XC_OFF   (LS_BIAS_OFF + 512 * 4)        // float [32][5]
#define LS_Z_OFF    (LS_XC_OFF + 32 * 5 * 4 + 64)  // float [32][520], 16B-aligned
#define LS_SMEM     (LS_Z_OFF + 32 * 520 * 4)

__global__ __launch_bounds__(256, 1) void lstm_kernel(const float* __restrict__ Whh,
                                                      const float* __restrict__ Wih,
                                                      const float* __restrict__ b,
                                                      float* __restrict__ outHT,
                                                      float* __restrict__ outCT) {
    extern __shared__ char sm[];
    half*  B     = reinterpret_cast<half*>(sm + LS_B_OFF);
    half*  Ast   = reinterpret_cast<half*>(sm + LS_AST_OFF);
    float* WihS  = reinterpret_cast<float*>(sm + LS_WIH_OFF);
    float* biasS = reinterpret_cast<float*>(sm + LS_BIAS_OFF);
    float* xc    = reinterpret_cast<float*>(sm + LS_XC_OFF);
    float* Z     = reinterpret_cast<float*>(sm + LS_Z_OFF);

    const int tid = threadIdx.x;
    const int wid = tid >> 5;
    const int row0 = blockIdx.x * 32;
    const int nrows = min(32, NN - row0);

    // Gate-column permutation: stored col s = nw*128 + q*32 + rr  <-  orig col c = q*128 + nw*32 + rr
    for (int idx = tid; idx < 128 * 512; idx += 256) {
        int k = idx >> 9, s = idx & 511;
        int nw = s >> 7, q = (s >> 5) & 3, rr = s & 31;
        int c = q * 128 + nw * 32 + rr;
        B[k * 520 + s] = __float2half(Whh[k * 512 + c]);
    }
    for (int idx = tid; idx < 5 * 512; idx += 256) {
        int k = idx >> 9, s = idx & 511;
        int nw = s >> 7, q = (s >> 5) & 3, rr = s & 31;
        int c = q * 128 + nw * 32 + rr;
        WihS[k * 512 + s] = Wih[k * 512 + c];
    }
    for (int s = tid; s < 512; s += 256) {
        int nw = s >> 7, q = (s >> 5) & 3, rr = s & 31;
        biasS[s] = b[q * 128 + nw * 32 + rr];
    }
    for (int idx = tid; idx < 32 * 136; idx += 256) Ast[idx] = __float2half(0.f);

    float creg[16];
#pragma unroll
    for (int e = 0; e < 16; e++) creg[e] = 0.f;

    __syncthreads();

    const int mw = wid >> 2;   // 0..1 -> 16-row group
    const int nw = wid & 3;    // 0..3 -> 128 stored cols

    for (int t = 0; t < TT; t++) {
        wmma::fragment<wmma::accumulator, 16, 16, 16, float> acc[8];
#pragma unroll
        for (int nt = 0; nt < 8; nt++) wmma::fill_fragment(acc[nt], 0.f);
#pragma unroll
        for (int k = 0; k < 8; k++) {
            wmma::fragment<wmma::matrix_a, 16, 16, 16, half, wmma::row_major> af;
            wmma::load_matrix_sync(af, Ast + (mw * 16) * 136 + k * 16, 136);
#pragma unroll
            for (int nt = 0; nt < 8; nt++) {
                wmma::fragment<wmma::matrix_b, 16, 16, 16, half, wmma::row_major> bf;
                wmma::load_matrix_sync(bf, B + (k * 16) * 520 + nw * 128 + nt * 16, 520);
                wmma::mma_sync(acc[nt], af, bf, acc[nt]);
            }
        }
#pragma unroll
        for (int nt = 0; nt < 8; nt++)
            wmma::store_matrix_sync(Z + (mw * 16) * 520 + nw * 128 + nt * 16, acc[nt], 520,
                                    wmma::mem_row_major);

        if (tid < 32 * DDYN) {
            int rr2 = tid / DDYN, k = tid % DDYN;
            xc[tid] = (rr2 < nrows) ? g_xs[((size_t)(row0 + rr2) * TT + t) * DDYN + k] : 0.f;
        }
        __syncthreads();

#pragma unroll
        for (int e = 0; e < 16; e++) {
            int idx = (e << 8) + tid;
            int row = idx >> 7, r = idx & 127;
            int sb = ((r >> 5) << 7) + (r & 31);
            const float* zr = Z + row * 520;
            const float* xr = xc + row * DDYN;
            float zi = zr[sb]      + biasS[sb];
            float zf = zr[sb + 32] + biasS[sb + 32];
            float zg = zr[sb + 64] + biasS[sb + 64];
            float zo = zr[sb + 96] + biasS[sb + 96];
#pragma unroll
            for (int k = 0; k < DDYN; k++) {
                float xv = xr[k];
                const float* wr = WihS + k * 512 + sb;
                zi = fmaf(xv, wr[0],  zi);
                zf = fmaf(xv, wr[32], zf);
                zg = fmaf(xv, wr[64], zg);
                zo = fmaf(xv, wr[96], zo);
            }
            float ig = sigm(zi), fg = sigm(zf), og = sigm(zo), gg = tanh_acc(zg);
            float c = fmaf(fg, creg[e], ig * gg);
            creg[e] = c;
            float h = og * tanh_acc(c);
            Ast[row * 136 + r] = __float2half(h);
            if (row < nrows) {
                g_hseq[((size_t)(row0 + row) * TT + t) * RR + r] = __float2half(h);
                if (t == TT - 1) {
                    outHT[(row0 + row) * RR + r] = h;
                    outCT[(row0 + row) * RR + r] = c;
                }
            }
        }
        __syncthreads();
    }
}

// ---------------- kernel 5: y = leaky(2h@lin_w + lin_b)@lin2_w + lin2_b ----------------
#define HD_B_OFF  0                            // half [128][136]
#define HD_Z_OFF  (HD_B_OFF + 128 * 136 * 2)   // float [64][136]
#define HD_LB_OFF (HD_Z_OFF + 64 * 136 * 4)    // float [128]
#define HD_L2_OFF (HD_LB_OFF + 128 * 4)        // float [128]
#define HD_SMEM   (HD_L2_OFF + 128 * 4)

__global__ __launch_bounds__(256) void head_kernel(const float* __restrict__ lin_w,
                                                   const float* __restrict__ lin_b,
                                                   const float* __restrict__ lin2_w,
                                                   const float* __restrict__ lin2_b,
                                                   float* __restrict__ y) {
    extern __shared__ char sm[];
    half*  Bh = reinterpret_cast<half*>(sm + HD_B_OFF);
    float* Zs = reinterpret_cast<float*>(sm + HD_Z_OFF);
    float* lb = reinterpret_cast<float*>(sm + HD_LB_OFF);
    float* l2 = reinterpret_cast<float*>(sm + HD_L2_OFF);
    const int tid = threadIdx.x, wid = tid >> 5, lane = tid & 31;

    for (int idx = tid; idx < 128 * 128; idx += 256) {
        int k = idx >> 7, n = idx & 127;
        Bh[k * 136 + n] = __float2half(2.f * lin_w[idx]);   // fold h_att = 2h
    }
    if (tid < 128) { lb[tid] = lin_b[tid]; l2[tid] = lin2_w[tid]; }
    __syncthreads();

    const int row0 = blockIdx.x * 64;
    const int mw = wid >> 1, nwk = wid & 1;
    wmma::fragment<wmma::accumulator, 16, 16, 16, float> acc[4];
#pragma unroll
    for (int nt = 0; nt < 4; nt++) wmma::fill_fragment(acc[nt], 0.f);
    const half* Ag = g_hseq + (size_t)(row0 + mw * 16) * RR;
#pragma unroll
    for (int k = 0; k < 8; k++) {
        wmma::fragment<wmma::matrix_a, 16, 16, 16, half, wmma::row_major> af;
        wmma::load_matrix_sync(af, Ag + k * 16, 128);
#pragma unroll
        for (int nt = 0; nt < 4; nt++) {
            wmma::fragment<wmma::matrix_b, 16, 16, 16, half, wmma::row_major> bf;
            wmma::load_matrix_sync(bf, Bh + (k * 16) * 136 + nwk * 64 + nt * 16, 136);
            wmma::mma_sync(acc[nt], af, bf, acc[nt]);
        }
    }
#pragma unroll
    for (int nt = 0; nt < 4; nt++)
        wmma::store_matrix_sync(Zs + (mw * 16) * 136 + nwk * 64 + nt * 16, acc[nt], 136,
                                wmma::mem_row_major);
    __syncthreads();

    const int row = wid * 8 + (lane >> 2);
    const int q = lane & 3;
    float a = 0.f;
    const float* zr  = Zs + row * 136 + q * 32;
    const float* lbp = lb + q * 32;
    const float* l2p = l2 + q * 32;
#pragma unroll
    for (int cc = 0; cc < 32; cc++) {
        float v = zr[cc] + lbp[cc];
        v = v >= 0.f ? v : 0.01f * v;
        a = fmaf(v, l2p[cc], a);
    }
    a += __shfl_xor_sync(0xffffffffu, a, 1);
    a += __shfl_xor_sync(0xffffffffu, a, 2);
    if (q == 0) y[row0 + row] = a + lin2_b[0];
}

// ---------------- launch ----------------
extern "C" void kernel_launch(void* const* d_in, const int* in_sizes, int n_in,
                              void* d_out, int out_size) {
    const float* dynamic = (const float*)d_in[0];
    const float* pop     = (const float*)d_in[1];
    const float* demo    = (const float*)d_in[2];
    const float* eco     = (const float*)d_in[3];
    const float* geo     = (const float*)d_in[4];
    const float* W_pop   = (const float*)d_in[5];
    const float* a_pop   = (const float*)d_in[6];
    const float* W_demo  = (const float*)d_in[7];
    const float* a_demo  = (const float*)d_in[8];
    const float* W_eco   = (const float*)d_in[9];
    const float* a_eco   = (const float*)d_in[10];
    const float* W_geo   = (const float*)d_in[11];
    const float* a_geo   = (const float*)d_in[12];
    const float* cw_w1   = (const float*)d_in[13];
    const float* cw_b1   = (const float*)d_in[14];
    const float* cw_w2   = (const float*)d_in[15];
    const float* cw_b2   = (const float*)d_in[16];
    const float* hw_w1   = (const float*)d_in[17];
    const float* hw_b1   = (const float*)d_in[18];
    const float* hw_w2   = (const float*)d_in[19];
    const float* hw_b2   = (const float*)d_in[20];
    const float* Wih     = (const float*)d_in[21];
    const float* Whh     = (const float*)d_in[22];
    const float* b_lstm  = (const float*)d_in[23];
    const float* lin_w   = (const float*)d_in[24];
    const float* lin_b   = (const float*)d_in[25];
    const float* lin2_w  = (const float*)d_in[26];
    const float* lin2_b  = (const float*)d_in[27];

    float* out  = (float*)d_out;
    float* y    = out;                               // N*T*1   = 192000
    float* dist = y + (size_t)NN * TT;               // N*N     = 9000000
    float* tw   = dist + (size_t)NN * NN;            // N*T*5   = 960000
    float* hT   = tw + (size_t)NN * TT * DDYN;       // N*R     = 384000
    float* cT   = hT + (size_t)NN * RR;              // N*R     = 384000

    cudaFuncSetAttribute(lstm_kernel, cudaFuncAttributeMaxDynamicSharedMemorySize, LS_SMEM);
    cudaFuncSetAttribute(head_kernel, cudaFuncAttributeMaxDynamicSharedMemorySize, HD_SMEM);

    svec_kernel<<<(NN + 255) / 256, 256>>>(pop, demo, eco, W_pop, a_pop, W_demo, a_demo,
                                           W_eco, a_eco);
    dist_kernel<<<NN, 256>>>(geo, W_geo, a_geo, dist);
    tw_kernel<<<(NN * TT) / 256, 256>>>(dynamic, cw_w1, cw_b1, cw_w2, cw_b2,
                                        hw_w1, hw_b1, hw_w2, hw_b2, tw);
    lstm_kernel<<<(NN + 31) / 32, 256, LS_SMEM>>>(Whh, Wih, b_lstm, hT, cT);
    head_kernel<<<(NN * TT) / 64, 256, HD_SMEM>>>(lin_w, lin_b, lin2_w, lin2_b, y);
}

// round 7
// speedup vs baseline: 1.0375x; 1.0375x over previous
#include <cuda_runtime.h>
#include <cuda_fp16.h>
#include <mma.h>

using namespace nvcuda;

#define NN   3000
#define TT   64
#define DDYN 5
#define RR   128

// ---------------- scratch (device globals; no allocations) ----------------
__device__ float  g_svec[6 * NN];                       // pop1,pop2,demo1,demo2,eco1,eco2
__device__ float  g_xs[(size_t)NN * TT * DDYN];         // total_weights * dynamic
__device__ __half g_hseq[(size_t)NN * TT * RR];         // LSTM hidden sequence (fp16)

// ---------------- math helpers ----------------
__device__ __forceinline__ float sigm(float x) {            // accurate, 2 MUFU
    return __fdividef(1.f, 1.f + __expf(-x));
}
__device__ __forceinline__ float tanh_acc(float x) {        // accurate, 2 MUFU
    return fmaf(2.f, sigm(2.f * x), -1.f);
}
__device__ __forceinline__ float leaky(float x) { return x >= 0.f ? x : 0.01f * x; }

// ---------------- kernel 1: rank-1 pair-score vectors ----------------
template <int D>
__device__ __forceinline__ void pair_s(const float* __restrict__ x,
                                       const float* __restrict__ W,
                                       const float* __restrict__ a,
                                       float& s1, float& s2) {
    float xv[D];
#pragma unroll
    for (int k = 0; k < D; k++) xv[k] = x[k];
    float t1 = 0.f, t2 = 0.f;
    for (int j = 0; j < D; j++) {
        float h = 0.f;
#pragma unroll
        for (int k = 0; k < D; k++) h = fmaf(xv[k], W[k * D + j], h);
        t1 = fmaf(h, a[j], t1);
        t2 = fmaf(h, a[D + j], t2);
    }
    s1 = t1; s2 = t2;
}

__global__ void svec_kernel(const float* __restrict__ pop, const float* __restrict__ demo,
                            const float* __restrict__ eco,
                            const float* __restrict__ W_pop, const float* __restrict__ a_pop,
                            const float* __restrict__ W_demo, const float* __restrict__ a_demo,
                            const float* __restrict__ W_eco, const float* __restrict__ a_eco) {
    int i = blockIdx.x * blockDim.x + threadIdx.x;
    if (i >= NN) return;
    float s1, s2;
    pair_s<16>(pop + i * 16, W_pop, a_pop, s1, s2);
    g_svec[0 * NN + i] = s1; g_svec[1 * NN + i] = s2;
    pair_s<32>(demo + i * 32, W_demo, a_demo, s1, s2);
    g_svec[2 * NN + i] = s1; g_svec[3 * NN + i] = s2;
    pair_s<16>(eco + i * 16, W_eco, a_eco, s1, s2);
    g_svec[4 * NN + i] = s1; g_svec[5 * NN + i] = s2;
}

// ---------------- kernel 2: fused score + softmax -> dist ----------------
__global__ __launch_bounds__(256) void dist_kernel(const float* __restrict__ geo,
                                                   const float* __restrict__ W_geo,
                                                   const float* __restrict__ a_geo,
                                                   float* __restrict__ dist) {
    const int i = blockIdx.x;
    const int tid = threadIdx.x;
    const float v0 = fmaf(W_geo[0], a_geo[0], W_geo[1] * a_geo[1]);
    const float v1 = fmaf(W_geo[2], a_geo[0], W_geo[3] * a_geo[1]);
    const float sp1 = g_svec[0 * NN + i];
    const float sd1 = g_svec[2 * NN + i];
    const float se1 = g_svec[4 * NN + i];
    const float2* grow = reinterpret_cast<const float2*>(geo) + (size_t)i * NN;

    float ev[12];
    float sum = 0.f;
#pragma unroll
    for (int k2 = 0; k2 < 12; k2++) {
        int j = tid + (k2 << 8);
        float e = 0.f;
        if (j < NN) {
            float2 g = __ldg(grow + j);
            float sg = fmaf(g.x, v0, g.y * v1);
            float a = sigm(sp1 + g_svec[1 * NN + j])
                    + sigm(sd1 + g_svec[3 * NN + j])
                    + sigm(se1 + g_svec[5 * NN + j])
                    + sigm(sg);
            e = __expf(a);
        }
        ev[k2] = e;
        sum += e;
    }
#pragma unroll
    for (int o = 16; o > 0; o >>= 1) sum += __shfl_xor_sync(0xffffffffu, sum, o);
    __shared__ float red[8];
    __shared__ float stot;
    if ((tid & 31) == 0) red[tid >> 5] = sum;
    __syncthreads();
    if (tid == 0) {
        float t2 = 0.f;
#pragma unroll
        for (int w = 0; w < 8; w++) t2 += red[w];
        stot = __fdividef(1.f, t2);
    }
    __syncthreads();
    const float inv = stot;
    float* drow = dist + (size_t)i * NN;
#pragma unroll
    for (int k2 = 0; k2 < 12; k2++) {
        int j = tid + (k2 << 8);
        if (j < NN) drow[j] = ev[k2] * inv;
    }
}

// ---------------- kernel 3: total_weights MLPs + scaled LSTM input ----------------
__global__ __launch_bounds__(256) void tw_kernel(const float* __restrict__ dyn,
        const float* __restrict__ cw_w1, const float* __restrict__ cw_b1,
        const float* __restrict__ cw_w2, const float* __restrict__ cw_b2,
        const float* __restrict__ hw_w1, const float* __restrict__ hw_b1,
        const float* __restrict__ hw_w2, const float* __restrict__ hw_b2,
        float* __restrict__ tw) {
    __shared__ float s_c1[128], s_cb1[128], s_c2[128];
    __shared__ float s_h1[4 * 128], s_hb1[128], s_h2[128 * 4];
    __shared__ float s_cb2, s_hb2[4];
    const int tid = threadIdx.x;
    for (int idx = tid; idx < 128; idx += 256) {
        s_c1[idx] = cw_w1[idx]; s_cb1[idx] = cw_b1[idx];
        s_c2[idx] = cw_w2[idx]; s_hb1[idx] = hw_b1[idx];
    }
    for (int idx = tid; idx < 512; idx += 256) { s_h1[idx] = hw_w1[idx]; s_h2[idx] = hw_w2[idx]; }
    if (tid == 0) s_cb2 = cw_b2[0];
    if (tid < 4) s_hb2[tid] = hw_b2[tid];
    __syncthreads();

    const int idx = blockIdx.x * 256 + tid;
    if (idx >= NN * TT) return;
    const float* d = dyn + (size_t)idx * DDYN;
    const float x0 = d[0], x1 = d[1], x2 = d[2], x3 = d[3], x4 = d[4];
    float ca = 0.f, o0 = 0.f, o1 = 0.f, o2 = 0.f, o3 = 0.f;
#pragma unroll 4
    for (int r = 0; r < 128; r++) {
        float hc = fmaf(x0, s_c1[r], s_cb1[r]);
        hc = leaky(hc);
        ca = fmaf(hc, s_c2[r], ca);
        float hh = s_hb1[r];
        hh = fmaf(x1, s_h1[r], hh);
        hh = fmaf(x2, s_h1[128 + r], hh);
        hh = fmaf(x3, s_h1[256 + r], hh);
        hh = fmaf(x4, s_h1[384 + r], hh);
        hh = leaky(hh);
        o0 = fmaf(hh, s_h2[r * 4 + 0], o0);
        o1 = fmaf(hh, s_h2[r * 4 + 1], o1);
        o2 = fmaf(hh, s_h2[r * 4 + 2], o2);
        o3 = fmaf(hh, s_h2[r * 4 + 3], o3);
    }
    const float w0 = sigm(ca + s_cb2);
    const float w1 = sigm(o0 + s_hb2[0]);
    const float w2 = sigm(o1 + s_hb2[1]);
    const float w3 = sigm(o2 + s_hb2[2]);
    const float w4 = sigm(o3 + s_hb2[3]);
    float* twp = tw + (size_t)idx * DDYN;
    twp[0] = w0; twp[1] = w1; twp[2] = w2; twp[3] = w3; twp[4] = w4;
    float* xp = g_xs + (size_t)idx * DDYN;
    xp[0] = w0 * x0; xp[1] = w1 * x1; xp[2] = w2 * x2; xp[3] = w3 * x3; xp[4] = w4 * x4;
}

// ---------------- kernel 4: persistent fp16-mma LSTM ----------------
// MMA computes ONLY h @ Whh (K=128) exactly as the verified round-3 build.
// Wih·x + bias are applied in the scalar fp32 epilogue (NO K-extension folding),
// but the per-thread Wih/bias values are held in REGISTERS (u = tid&127 is fixed).
#define BSTR 520   // halves
#define ASTR 136   // halves
#define ZSTR 520   // floats

#define LS_B_OFF   0
#define LS_AST_OFF (LS_B_OFF + 128 * BSTR * 2)         // 133120
#define LS_XC_OFF  (LS_AST_OFF + 32 * ASTR * 2)        // +8704  -> 141824
#define LS_Z_OFF   (LS_XC_OFF + 32 * DDYN * 4 + 64)    // +704   -> 142528
#define LS_SMEM    (LS_Z_OFF + 32 * ZSTR * 4)          // +66560 -> 209088 B

__global__ __launch_bounds__(256, 1) void lstm_kernel(const float* __restrict__ Whh,
                                                      const float* __restrict__ Wih,
                                                      const float* __restrict__ b,
                                                      float* __restrict__ outHT,
                                                      float* __restrict__ outCT) {
    extern __shared__ char sm[];
    half*  B   = reinterpret_cast<half*>(sm + LS_B_OFF);
    half*  Ast = reinterpret_cast<half*>(sm + LS_AST_OFF);
    float* xc  = reinterpret_cast<float*>(sm + LS_XC_OFF);
    float* Z   = reinterpret_cast<float*>(sm + LS_Z_OFF);

    const int tid = threadIdx.x;
    const int w   = tid >> 5;            // warp 0..7: owns N-cols w*64..w*64+64
    const int row0  = blockIdx.x * 32;
    const int nrows = min(32, NN - row0);

    // B = Whh in fp16, natural column order (i|f|g|o across 0..511)
    for (int idx = tid; idx < 128 * 512; idx += 256) {
        int k = idx >> 9, c = idx & 511;
        B[k * BSTR + c] = __float2half(Whh[k * 512 + c]);
    }
    // Ast init: h = 0 (cols 0..127), pad 0
    for (int idx = tid; idx < 32 * ASTR; idx += 256) Ast[idx] = __float2half(0.f);

    // Per-thread fixed unit column u; Wih/bias columns {u, u+128, u+256, u+384} in registers (fp32 exact)
    const int u = tid & 127;
    float wih_r[DDYN][4];
    float bias_r[4];
#pragma unroll
    for (int g = 0; g < 4; g++) {
        bias_r[g] = b[u + 128 * g];
#pragma unroll
        for (int k = 0; k < DDYN; k++) wih_r[k][g] = Wih[k * 512 + u + 128 * g];
    }

    float creg[16];
#pragma unroll
    for (int e = 0; e < 16; e++) creg[e] = 0.f;

    __syncthreads();

    const int rbase = tid >> 7;          // 0 or 1
    const int prow = tid / DDYN, pk = tid - prow * DDYN;

    for (int t = 0; t < TT; t++) {
        // ---- MMA: Z(32x512) = Ast(32x128) @ B(128x512); warp w: 2 m-tiles x 4 n-tiles ----
        wmma::fragment<wmma::accumulator, 16, 16, 16, float> acc[2][4];
#pragma unroll
        for (int mh = 0; mh < 2; mh++)
#pragma unroll
            for (int nt = 0; nt < 4; nt++) wmma::fill_fragment(acc[mh][nt], 0.f);
#pragma unroll
        for (int k = 0; k < 8; k++) {
            wmma::fragment<wmma::matrix_a, 16, 16, 16, half, wmma::row_major> af0, af1;
            wmma::load_matrix_sync(af0, Ast + k * 16, ASTR);
            wmma::load_matrix_sync(af1, Ast + 16 * ASTR + k * 16, ASTR);
#pragma unroll
            for (int nt = 0; nt < 4; nt++) {
                wmma::fragment<wmma::matrix_b, 16, 16, 16, half, wmma::row_major> bf;
                wmma::load_matrix_sync(bf, B + (k * 16) * BSTR + w * 64 + nt * 16, BSTR);
                wmma::mma_sync(acc[0][nt], af0, bf, acc[0][nt]);
                wmma::mma_sync(acc[1][nt], af1, bf, acc[1][nt]);
            }
        }
#pragma unroll
        for (int mh = 0; mh < 2; mh++)
#pragma unroll
            for (int nt = 0; nt < 4; nt++)
                wmma::store_matrix_sync(Z + (mh * 16) * ZSTR + w * 64 + nt * 16,
                                        acc[mh][nt], ZSTR, wmma::mem_row_major);

        // stage x(t) for the epilogue (overlaps with MMA tail)
        if (tid < 32 * DDYN)
            xc[tid] = (prow < nrows) ? g_xs[((size_t)(row0 + prow) * TT + t) * DDYN + pk] : 0.f;
        __syncthreads();

        // ---- epilogue: z -> gates -> c,h (fp32 scalar, Wih/bias from registers) ----
        const bool last = (t == TT - 1);
#pragma unroll
        for (int e = 0; e < 16; e++) {
            int row = 2 * e + rbase;
            const float* zr = Z + row * ZSTR + u;
            float zi = zr[0]   + bias_r[0];
            float zf = zr[128] + bias_r[1];
            float zg = zr[256] + bias_r[2];
            float zo = zr[384] + bias_r[3];
            const float* xr = xc + row * DDYN;
#pragma unroll
            for (int k = 0; k < DDYN; k++) {
                float xv = xr[k];
                zi = fmaf(xv, wih_r[k][0], zi);
                zf = fmaf(xv, wih_r[k][1], zf);
                zg = fmaf(xv, wih_r[k][2], zg);
                zo = fmaf(xv, wih_r[k][3], zo);
            }
            float ig = sigm(zi), fg = sigm(zf), og = sigm(zo), gg = tanh_acc(zg);
            float c  = fmaf(fg, creg[e], ig * gg);
            creg[e] = c;
            float h  = og * tanh_acc(c);
            half hh  = __float2half(h);
            Ast[row * ASTR + u] = hh;
            if (row < nrows) {
                g_hseq[((size_t)(row0 + row) * TT + t) * RR + u] = hh;
                if (last) {
                    outHT[(row0 + row) * RR + u] = h;
                    outCT[(row0 + row) * RR + u] = c;
                }
            }
        }
        __syncthreads();
    }
}

// ---------------- kernel 5: y = leaky(2h@lin_w + lin_b)@lin2_w + lin2_b ----------------
#define HD_B_OFF  0                            // half [128][136]
#define HD_Z_OFF  (HD_B_OFF + 128 * 136 * 2)   // float [64][136]
#define HD_LB_OFF (HD_Z_OFF + 64 * 136 * 4)    // float [128]
#define HD_L2_OFF (HD_LB_OFF + 128 * 4)        // float [128]
#define HD_SMEM   (HD_L2_OFF + 128 * 4)

__global__ __launch_bounds__(256) void head_kernel(const float* __restrict__ lin_w,
                                                   const float* __restrict__ lin_b,
                                                   const float* __restrict__ lin2_w,
                                                   const float* __restrict__ lin2_b,
                                                   float* __restrict__ y) {
    extern __shared__ char sm[];
    half*  Bh = reinterpret_cast<half*>(sm + HD_B_OFF);
    float* Zs = reinterpret_cast<float*>(sm + HD_Z_OFF);
    float* lb = reinterpret_cast<float*>(sm + HD_LB_OFF);
    float* l2 = reinterpret_cast<float*>(sm + HD_L2_OFF);
    const int tid = threadIdx.x, wid = tid >> 5, lane = tid & 31;

    for (int idx = tid; idx < 128 * 128; idx += 256) {
        int k = idx >> 7, n = idx & 127;
        Bh[k * 136 + n] = __float2half(2.f * lin_w[idx]);   // fold h_att = 2h
    }
    if (tid < 128) { lb[tid] = lin_b[tid]; l2[tid] = lin2_w[tid]; }
    __syncthreads();

    const int row0 = blockIdx.x * 64;
    const int mw = wid >> 1, nwk = wid & 1;
    wmma::fragment<wmma::accumulator, 16, 16, 16, float> acc[4];
#pragma unroll
    for (int nt = 0; nt < 4; nt++) wmma::fill_fragment(acc[nt], 0.f);
    const half* Ag = g_hseq + (size_t)(row0 + mw * 16) * RR;
#pragma unroll
    for (int k = 0; k < 8; k++) {
        wmma::fragment<wmma::matrix_a, 16, 16, 16, half, wmma::row_major> af;
        wmma::load_matrix_sync(af, Ag + k * 16, 128);
#pragma unroll
        for (int nt = 0; nt < 4; nt++) {
            wmma::fragment<wmma::matrix_b, 16, 16, 16, half, wmma::row_major> bf;
            wmma::load_matrix_sync(bf, Bh + (k * 16) * 136 + nwk * 64 + nt * 16, 136);
            wmma::mma_sync(acc[nt], af, bf, acc[nt]);
        }
    }
#pragma unroll
    for (int nt = 0; nt < 4; nt++)
        wmma::store_matrix_sync(Zs + (mw * 16) * 136 + nwk * 64 + nt * 16, acc[nt], 136,
                                wmma::mem_row_major);
    __syncthreads();

    const int row = wid * 8 + (lane >> 2);
    const int q = lane & 3;
    float a = 0.f;
    const float* zr  = Zs + row * 136 + q * 32;
    const float* lbp = lb + q * 32;
    const float* l2p = l2 + q * 32;
#pragma unroll
    for (int cc = 0; cc < 32; cc++) {
        float v = zr[cc] + lbp[cc];
        v = v >= 0.f ? v : 0.01f * v;
        a = fmaf(v, l2p[cc], a);
    }
    a += __shfl_xor_sync(0xffffffffu, a, 1);
    a += __shfl_xor_sync(0xffffffffu, a, 2);
    if (q == 0) y[row0 + row] = a + lin2_b[0];
}

// ---------------- launch ----------------
extern "C" void kernel_launch(void* const* d_in, const int* in_sizes, int n_in,
                              void* d_out, int out_size) {
    const float* dynamic = (const float*)d_in[0];
    const float* pop     = (const float*)d_in[1];
    const float* demo    = (const float*)d_in[2];
    const float* eco     = (const float*)d_in[3];
    const float* geo     = (const float*)d_in[4];
    const float* W_pop   = (const float*)d_in[5];
    const float* a_pop   = (const float*)d_in[6];
    const float* W_demo  = (const float*)d_in[7];
    const float* a_demo  = (const float*)d_in[8];
    const float* W_eco   = (const float*)d_in[9];
    const float* a_eco   = (const float*)d_in[10];
    const float* W_geo   = (const float*)d_in[11];
    const float* a_geo   = (const float*)d_in[12];
    const float* cw_w1   = (const float*)d_in[13];
    const float* cw_b1   = (const float*)d_in[14];
    const float* cw_w2   = (const float*)d_in[15];
    const float* cw_b2   = (const float*)d_in[16];
    const float* hw_w1   = (const float*)d_in[17];
    const float* hw_b1   = (const float*)d_in[18];
    const float* hw_w2   = (const float*)d_in[19];
    const float* hw_b2   = (const float*)d_in[20];
    const float* Wih     = (const float*)d_in[21];
    const float* Whh     = (const float*)d_in[22];
    const float* b_lstm  = (const float*)d_in[23];
    const float* lin_w   = (const float*)d_in[24];
    const float* lin_b   = (const float*)d_in[25];
    const float* lin2_w  = (const float*)d_in[26];
    const float* lin2_b  = (const float*)d_in[27];

    float* out  = (float*)d_out;
    float* y    = out;                               // N*T*1   = 192000
    float* dist = y + (size_t)NN * TT;               // N*N     = 9000000
    float* tw   = dist + (size_t)NN * NN;            // N*T*5   = 960000
    float* hT   = tw + (size_t)NN * TT * DDYN;       // N*R     = 384000
    float* cT   = hT + (size_t)NN * RR;              // N*R     = 384000

    cudaFuncSetAttribute(lstm_kernel, cudaFuncAttributeMaxDynamicSharedMemorySize, LS_SMEM);
    cudaFuncSetAttribute(head_kernel, cudaFuncAttributeMaxDynamicSharedMemorySize, HD_SMEM);

    svec_kernel<<<(NN + 255) / 256, 256>>>(pop, demo, eco, W_pop, a_pop, W_demo, a_demo,
                                           W_eco, a_eco);
    dist_kernel<<<NN, 256>>>(geo, W_geo, a_geo, dist);
    tw_kernel<<<(NN * TT) / 256, 256>>>(dynamic, cw_w1, cw_b1, cw_w2, cw_b2,
                                        hw_w1, hw_b1, hw_w2, hw_b2, tw);
    lstm_kernel<<<(NN + 31) / 32, 256, LS_SMEM>>>(Whh, Wih, b_lstm, hT, cT);
    head_kernel<<<(NN * TT) / 64, 256, HD_SMEM>>>(lin_w, lin_b, lin2_w, lin2_b, y);
}

// round 8
// speedup vs baseline: 1.1921x; 1.1490x over previous
#include <cuda_runtime.h>
#include <cuda_fp16.h>
#include <mma.h>

using namespace nvcuda;

#define NN   3000
#define TT   64
#define DDYN 5
#define RR   128

// ---------------- scratch (device globals; no allocations) ----------------
__device__ float  g_svec[6 * NN];                       // pop1,pop2,demo1,demo2,eco1,eco2
__device__ float  g_xs[(size_t)NN * TT * DDYN];         // total_weights * dynamic
__device__ __half g_hseq[(size_t)NN * TT * RR];         // LSTM hidden sequence (fp16)

// ---------------- math helpers ----------------
__device__ __forceinline__ float sigm(float x) {            // accurate, 2 MUFU
    return __fdividef(1.f, 1.f + __expf(-x));
}
__device__ __forceinline__ float tanh_acc(float x) {        // accurate, 2 MUFU
    return fmaf(2.f, sigm(2.f * x), -1.f);
}
__device__ __forceinline__ float leaky(float x) { return x >= 0.f ? x : 0.01f * x; }

// ---------------- kernel 1: rank-1 pair-score vectors ----------------
template <int D>
__device__ __forceinline__ void pair_s(const float* __restrict__ x,
                                       const float* __restrict__ W,
                                       const float* __restrict__ a,
                                       float& s1, float& s2) {
    float xv[D];
#pragma unroll
    for (int k = 0; k < D; k++) xv[k] = x[k];
    float t1 = 0.f, t2 = 0.f;
    for (int j = 0; j < D; j++) {
        float h = 0.f;
#pragma unroll
        for (int k = 0; k < D; k++) h = fmaf(xv[k], W[k * D + j], h);
        t1 = fmaf(h, a[j], t1);
        t2 = fmaf(h, a[D + j], t2);
    }
    s1 = t1; s2 = t2;
}

__global__ void svec_kernel(const float* __restrict__ pop, const float* __restrict__ demo,
                            const float* __restrict__ eco,
                            const float* __restrict__ W_pop, const float* __restrict__ a_pop,
                            const float* __restrict__ W_demo, const float* __restrict__ a_demo,
                            const float* __restrict__ W_eco, const float* __restrict__ a_eco) {
    int i = blockIdx.x * blockDim.x + threadIdx.x;
    if (i >= NN) return;
    float s1, s2;
    pair_s<16>(pop + i * 16, W_pop, a_pop, s1, s2);
    g_svec[0 * NN + i] = s1; g_svec[1 * NN + i] = s2;
    pair_s<32>(demo + i * 32, W_demo, a_demo, s1, s2);
    g_svec[2 * NN + i] = s1; g_svec[3 * NN + i] = s2;
    pair_s<16>(eco + i * 16, W_eco, a_eco, s1, s2);
    g_svec[4 * NN + i] = s1; g_svec[5 * NN + i] = s2;
}

// ---------------- kernel 2: fused score + softmax -> dist ----------------
__global__ __launch_bounds__(256) void dist_kernel(const float* __restrict__ geo,
                                                   const float* __restrict__ W_geo,
                                                   const float* __restrict__ a_geo,
                                                   float* __restrict__ dist) {
    const int i = blockIdx.x;
    const int tid = threadIdx.x;
    const float v0 = fmaf(W_geo[0], a_geo[0], W_geo[1] * a_geo[1]);
    const float v1 = fmaf(W_geo[2], a_geo[0], W_geo[3] * a_geo[1]);
    const float sp1 = g_svec[0 * NN + i];
    const float sd1 = g_svec[2 * NN + i];
    const float se1 = g_svec[4 * NN + i];
    const float2* grow = reinterpret_cast<const float2*>(geo) + (size_t)i * NN;

    float ev[12];
    float sum = 0.f;
#pragma unroll
    for (int k2 = 0; k2 < 12; k2++) {
        int j = tid + (k2 << 8);
        float e = 0.f;
        if (j < NN) {
            float2 g = __ldg(grow + j);
            float sg = fmaf(g.x, v0, g.y * v1);
            float a = sigm(sp1 + g_svec[1 * NN + j])
                    + sigm(sd1 + g_svec[3 * NN + j])
                    + sigm(se1 + g_svec[5 * NN + j])
                    + sigm(sg);
            e = __expf(a);
        }
        ev[k2] = e;
        sum += e;
    }
#pragma unroll
    for (int o = 16; o > 0; o >>= 1) sum += __shfl_xor_sync(0xffffffffu, sum, o);
    __shared__ float red[8];
    __shared__ float stot;
    if ((tid & 31) == 0) red[tid >> 5] = sum;
    __syncthreads();
    if (tid == 0) {
        float t2 = 0.f;
#pragma unroll
        for (int w = 0; w < 8; w++) t2 += red[w];
        stot = __fdividef(1.f, t2);
    }
    __syncthreads();
    const float inv = stot;
    float* drow = dist + (size_t)i * NN;
#pragma unroll
    for (int k2 = 0; k2 < 12; k2++) {
        int j = tid + (k2 << 8);
        if (j < NN) drow[j] = ev[k2] * inv;
    }
}

// ---------------- kernel 3: total_weights MLPs + scaled LSTM input ----------------
__global__ __launch_bounds__(256) void tw_kernel(const float* __restrict__ dyn,
        const float* __restrict__ cw_w1, const float* __restrict__ cw_b1,
        const float* __restrict__ cw_w2, const float* __restrict__ cw_b2,
        const float* __restrict__ hw_w1, const float* __restrict__ hw_b1,
        const float* __restrict__ hw_w2, const float* __restrict__ hw_b2,
        float* __restrict__ tw) {
    __shared__ float s_c1[128], s_cb1[128], s_c2[128];
    __shared__ float s_h1[4 * 128], s_hb1[128], s_h2[128 * 4];
    __shared__ float s_cb2, s_hb2[4];
    const int tid = threadIdx.x;
    for (int idx = tid; idx < 128; idx += 256) {
        s_c1[idx] = cw_w1[idx]; s_cb1[idx] = cw_b1[idx];
        s_c2[idx] = cw_w2[idx]; s_hb1[idx] = hw_b1[idx];
    }
    for (int idx = tid; idx < 512; idx += 256) { s_h1[idx] = hw_w1[idx]; s_h2[idx] = hw_w2[idx]; }
    if (tid == 0) s_cb2 = cw_b2[0];
    if (tid < 4) s_hb2[tid] = hw_b2[tid];
    __syncthreads();

    const int idx = blockIdx.x * 256 + tid;
    if (idx >= NN * TT) return;
    const float* d = dyn + (size_t)idx * DDYN;
    const float x0 = d[0], x1 = d[1], x2 = d[2], x3 = d[3], x4 = d[4];
    float ca = 0.f, o0 = 0.f, o1 = 0.f, o2 = 0.f, o3 = 0.f;
#pragma unroll 4
    for (int r = 0; r < 128; r++) {
        float hc = fmaf(x0, s_c1[r], s_cb1[r]);
        hc = leaky(hc);
        ca = fmaf(hc, s_c2[r], ca);
        float hh = s_hb1[r];
        hh = fmaf(x1, s_h1[r], hh);
        hh = fmaf(x2, s_h1[128 + r], hh);
        hh = fmaf(x3, s_h1[256 + r], hh);
        hh = fmaf(x4, s_h1[384 + r], hh);
        hh = leaky(hh);
        o0 = fmaf(hh, s_h2[r * 4 + 0], o0);
        o1 = fmaf(hh, s_h2[r * 4 + 1], o1);
        o2 = fmaf(hh, s_h2[r * 4 + 2], o2);
        o3 = fmaf(hh, s_h2[r * 4 + 3], o3);
    }
    const float w0 = sigm(ca + s_cb2);
    const float w1 = sigm(o0 + s_hb2[0]);
    const float w2 = sigm(o1 + s_hb2[1]);
    const float w3 = sigm(o2 + s_hb2[2]);
    const float w4 = sigm(o3 + s_hb2[3]);
    float* twp = tw + (size_t)idx * DDYN;
    twp[0] = w0; twp[1] = w1; twp[2] = w2; twp[3] = w3; twp[4] = w4;
    float* xp = g_xs + (size_t)idx * DDYN;
    xp[0] = w0 * x0; xp[1] = w1 * x1; xp[2] = w2 * x2; xp[3] = w3 * x3; xp[4] = w4 * x4;
}

// ---------------- kernel 4: persistent fp16-mma LSTM (512 threads, latency-hiding) ----
// Same math as the verified build: MMA = h @ Whh only; Wih·x + bias in fp32 epilogue
// from per-thread registers. 16 warps: warp w owns N-cols w*32..w*32+32, both m-tiles.
#define BSTR 520   // halves
#define ASTR 136   // halves
#define ZSTR 520   // floats

#define LS_B_OFF   0
#define LS_AST_OFF (LS_B_OFF + 128 * BSTR * 2)         // 133120
#define LS_XC_OFF  (LS_AST_OFF + 32 * ASTR * 2)        // +8704  -> 141824
#define LS_Z_OFF   (LS_XC_OFF + 32 * DDYN * 4 + 64)    // +704   -> 142528
#define LS_SMEM    (LS_Z_OFF + 32 * ZSTR * 4)          // +66560 -> 209088 B

__global__ __launch_bounds__(512, 1) void lstm_kernel(const float* __restrict__ Whh,
                                                      const float* __restrict__ Wih,
                                                      const float* __restrict__ b,
                                                      float* __restrict__ outHT,
                                                      float* __restrict__ outCT) {
    extern __shared__ char sm[];
    half*  B   = reinterpret_cast<half*>(sm + LS_B_OFF);
    half*  Ast = reinterpret_cast<half*>(sm + LS_AST_OFF);
    float* xc  = reinterpret_cast<float*>(sm + LS_XC_OFF);
    float* Z   = reinterpret_cast<float*>(sm + LS_Z_OFF);

    const int tid = threadIdx.x;
    const int w   = tid >> 5;            // warp 0..15: owns N-cols w*32..w*32+32
    const int row0  = blockIdx.x * 32;
    const int nrows = min(32, NN - row0);

    // B = Whh in fp16, natural column order (i|f|g|o across 0..511)
    for (int idx = tid; idx < 128 * 512; idx += 512) {
        int k = idx >> 9, c = idx & 511;
        B[k * BSTR + c] = __float2half(Whh[k * 512 + c]);
    }
    // Ast init: h = 0 (cols 0..127), pad 0
    for (int idx = tid; idx < 32 * ASTR; idx += 512) Ast[idx] = __float2half(0.f);

    // Per-thread fixed unit column u; Wih/bias columns {u, u+128, u+256, u+384} in registers
    const int u = tid & 127;
    float wih_r[DDYN][4];
    float bias_r[4];
#pragma unroll
    for (int g = 0; g < 4; g++) {
        bias_r[g] = b[u + 128 * g];
#pragma unroll
        for (int k = 0; k < DDYN; k++) wih_r[k][g] = Wih[k * 512 + u + 128 * g];
    }

    float creg[8];
#pragma unroll
    for (int e = 0; e < 8; e++) creg[e] = 0.f;

    __syncthreads();

    const int rbase = tid >> 7;          // 0..3
    const int prow = tid / DDYN, pk = tid - prow * DDYN;

    for (int t = 0; t < TT; t++) {
        // ---- MMA: Z(32x512) = Ast(32x128) @ B(128x512); warp w: 2 m-tiles x 2 n-tiles ----
        wmma::fragment<wmma::accumulator, 16, 16, 16, float> acc[2][2];
#pragma unroll
        for (int mh = 0; mh < 2; mh++)
#pragma unroll
            for (int nt = 0; nt < 2; nt++) wmma::fill_fragment(acc[mh][nt], 0.f);
#pragma unroll
        for (int k = 0; k < 8; k++) {
            wmma::fragment<wmma::matrix_a, 16, 16, 16, half, wmma::row_major> af0, af1;
            wmma::load_matrix_sync(af0, Ast + k * 16, ASTR);
            wmma::load_matrix_sync(af1, Ast + 16 * ASTR + k * 16, ASTR);
#pragma unroll
            for (int nt = 0; nt < 2; nt++) {
                wmma::fragment<wmma::matrix_b, 16, 16, 16, half, wmma::row_major> bf;
                wmma::load_matrix_sync(bf, B + (k * 16) * BSTR + w * 32 + nt * 16, BSTR);
                wmma::mma_sync(acc[0][nt], af0, bf, acc[0][nt]);
                wmma::mma_sync(acc[1][nt], af1, bf, acc[1][nt]);
            }
        }
#pragma unroll
        for (int mh = 0; mh < 2; mh++)
#pragma unroll
            for (int nt = 0; nt < 2; nt++)
                wmma::store_matrix_sync(Z + (mh * 16) * ZSTR + w * 32 + nt * 16,
                                        acc[mh][nt], ZSTR, wmma::mem_row_major);

        // stage x(t) for the epilogue (overlaps with MMA tail)
        if (tid < 32 * DDYN)
            xc[tid] = (prow < nrows) ? g_xs[((size_t)(row0 + prow) * TT + t) * DDYN + pk] : 0.f;
        __syncthreads();

        // ---- epilogue: z -> gates -> c,h (fp32 scalar, Wih/bias from registers) ----
        const bool last = (t == TT - 1);
#pragma unroll
        for (int e = 0; e < 8; e++) {
            int row = 4 * e + rbase;
            const float* zr = Z + row * ZSTR + u;
            float zi = zr[0]   + bias_r[0];
            float zf = zr[128] + bias_r[1];
            float zg = zr[256] + bias_r[2];
            float zo = zr[384] + bias_r[3];
            const float* xr = xc + row * DDYN;
#pragma unroll
            for (int k = 0; k < DDYN; k++) {
                float xv = xr[k];
                zi = fmaf(xv, wih_r[k][0], zi);
                zf = fmaf(xv, wih_r[k][1], zf);
                zg = fmaf(xv, wih_r[k][2], zg);
                zo = fmaf(xv, wih_r[k][3], zo);
            }
            float ig = sigm(zi), fg = sigm(zf), og = sigm(zo), gg = tanh_acc(zg);
            float c  = fmaf(fg, creg[e], ig * gg);
            creg[e] = c;
            float h  = og * tanh_acc(c);
            half hh  = __float2half(h);
            Ast[row * ASTR + u] = hh;
            if (row < nrows) {
                g_hseq[((size_t)(row0 + row) * TT + t) * RR + u] = hh;
                if (last) {
                    outHT[(row0 + row) * RR + u] = h;
                    outCT[(row0 + row) * RR + u] = c;
                }
            }
        }
        __syncthreads();
    }
}

// ---------------- kernel 5: y = leaky(2h@lin_w + lin_b)@lin2_w + lin2_b ----------------
#define HD_B_OFF  0                            // half [128][136]
#define HD_Z_OFF  (HD_B_OFF + 128 * 136 * 2)   // float [64][136]
#define HD_LB_OFF (HD_Z_OFF + 64 * 136 * 4)    // float [128]
#define HD_L2_OFF (HD_LB_OFF + 128 * 4)        // float [128]
#define HD_SMEM   (HD_L2_OFF + 128 * 4)

__global__ __launch_bounds__(256) void head_kernel(const float* __restrict__ lin_w,
                                                   const float* __restrict__ lin_b,
                                                   const float* __restrict__ lin2_w,
                                                   const float* __restrict__ lin2_b,
                                                   float* __restrict__ y) {
    extern __shared__ char sm[];
    half*  Bh = reinterpret_cast<half*>(sm + HD_B_OFF);
    float* Zs = reinterpret_cast<float*>(sm + HD_Z_OFF);
    float* lb = reinterpret_cast<float*>(sm + HD_LB_OFF);
    float* l2 = reinterpret_cast<float*>(sm + HD_L2_OFF);
    const int tid = threadIdx.x, wid = tid >> 5, lane = tid & 31;

    for (int idx = tid; idx < 128 * 128; idx += 256) {
        int k = idx >> 7, n = idx & 127;
        Bh[k * 136 + n] = __float2half(2.f * lin_w[idx]);   // fold h_att = 2h
    }
    if (tid < 128) { lb[tid] = lin_b[tid]; l2[tid] = lin2_w[tid]; }
    __syncthreads();

    const int row0 = blockIdx.x * 64;
    const int mw = wid >> 1, nwk = wid & 1;
    wmma::fragment<wmma::accumulator, 16, 16, 16, float> acc[4];
#pragma unroll
    for (int nt = 0; nt < 4; nt++) wmma::fill_fragment(acc[nt], 0.f);
    const half* Ag = g_hseq + (size_t)(row0 + mw * 16) * RR;
#pragma unroll
    for (int k = 0; k < 8; k++) {
        wmma::fragment<wmma::matrix_a, 16, 16, 16, half, wmma::row_major> af;
        wmma::load_matrix_sync(af, Ag + k * 16, 128);
#pragma unroll
        for (int nt = 0; nt < 4; nt++) {
            wmma::fragment<wmma::matrix_b, 16, 16, 16, half, wmma::row_major> bf;
            wmma::load_matrix_sync(bf, Bh + (k * 16) * 136 + nwk * 64 + nt * 16, 136);
            wmma::mma_sync(acc[nt], af, bf, acc[nt]);
        }
    }
#pragma unroll
    for (int nt = 0; nt < 4; nt++)
        wmma::store_matrix_sync(Zs + (mw * 16) * 136 + nwk * 64 + nt * 16, acc[nt], 136,
                                wmma::mem_row_major);
    __syncthreads();

    const int row = wid * 8 + (lane >> 2);
    const int q = lane & 3;
    float a = 0.f;
    const float* zr  = Zs + row * 136 + q * 32;
    const float* lbp = lb + q * 32;
    const float* l2p = l2 + q * 32;
#pragma unroll
    for (int cc = 0; cc < 32; cc++) {
        float v = zr[cc] + lbp[cc];
        v = v >= 0.f ? v : 0.01f * v;
        a = fmaf(v, l2p[cc], a);
    }
    a += __shfl_xor_sync(0xffffffffu, a, 1);
    a += __shfl_xor_sync(0xffffffffu, a, 2);
    if (q == 0) y[row0 + row] = a + lin2_b[0];
}

// ---------------- launch ----------------
extern "C" void kernel_launch(void* const* d_in, const int* in_sizes, int n_in,
                              void* d_out, int out_size) {
    const float* dynamic = (const float*)d_in[0];
    const float* pop     = (const float*)d_in[1];
    const float* demo    = (const float*)d_in[2];
    const float* eco     = (const float*)d_in[3];
    const float* geo     = (const float*)d_in[4];
    const float* W_pop   = (const float*)d_in[5];
    const float* a_pop   = (const float*)d_in[6];
    const float* W_demo  = (const float*)d_in[7];
    const float* a_demo  = (const float*)d_in[8];
    const float* W_eco   = (const float*)d_in[9];
    const float* a_eco   = (const float*)d_in[10];
    const float* W_geo   = (const float*)d_in[11];
    const float* a_geo   = (const float*)d_in[12];
    const float* cw_w1   = (const float*)d_in[13];
    const float* cw_b1   = (const float*)d_in[14];
    const float* cw_w2   = (const float*)d_in[15];
    const float* cw_b2   = (const float*)d_in[16];
    const float* hw_w1   = (const float*)d_in[17];
    const float* hw_b1   = (const float*)d_in[18];
    const float* hw_w2   = (const float*)d_in[19];
    const float* hw_b2   = (const float*)d_in[20];
    const float* Wih     = (const float*)d_in[21];
    const float* Whh     = (const float*)d_in[22];
    const float* b_lstm  = (const float*)d_in[23];
    const float* lin_w   = (const float*)d_in[24];
    const float* lin_b   = (const float*)d_in[25];
    const float* lin2_w  = (const float*)d_in[26];
    const float* lin2_b  = (const float*)d_in[27];

    float* out  = (float*)d_out;
    float* y    = out;                               // N*T*1   = 192000
    float* dist = y + (size_t)NN * TT;               // N*N     = 9000000
    float* tw   = dist + (size_t)NN * NN;            // N*T*5   = 960000
    float* hT   = tw + (size_t)NN * TT * DDYN;       // N*R     = 384000
    float* cT   = hT + (size_t)NN * RR;              // N*R     = 384000

    cudaFuncSetAttribute(lstm_kernel, cudaFuncAttributeMaxDynamicSharedMemorySize, LS_SMEM);
    cudaFuncSetAttribute(head_kernel, cudaFuncAttributeMaxDynamicSharedMemorySize, HD_SMEM);

    svec_kernel<<<(NN + 255) / 256, 256>>>(pop, demo, eco, W_pop, a_pop, W_demo, a_demo,
                                           W_eco, a_eco);
    dist_kernel<<<NN, 256>>>(geo, W_geo, a_geo, dist);
    tw_kernel<<<(NN * TT) / 256, 256>>>(dynamic, cw_w1, cw_b1, cw_w2, cw_b2,
                                        hw_w1, hw_b1, hw_w2, hw_b2, tw);
    lstm_kernel<<<(NN + 31) / 32, 512, LS_SMEM>>>(Whh, Wih, b_lstm, hT, cT);
    head_kernel<<<(NN * TT) / 64, 256, HD_SMEM>>>(lin_w, lin_b, lin2_w, lin2_b, y);
}